// round 1
// baseline (speedup 1.0000x reference)
#include <cuda_runtime.h>
#include <cuda_bf16.h>

// ContrastHead: neighbor-contrastive loss.
//   N=200000 points, K=16 neighbors, C=32 features, T=0.1, weight=0.1, eps=1e-8
// Inputs (metadata order): features f32 [N*C], labels i32 [N], neighbor_idx [N*K]
//   (neighbor_idx may be int32 or int64 depending on JAX x64 config -> runtime detect)
// Output: 1 float (scalar loss)

#define KNB 16
#define CF  32

__device__ double g_num;
__device__ double g_den;
__device__ int    g_is64;

// Zero accumulators and detect neighbor_idx dtype.
// If stored as int64 (values < N < 2^31, non-negative), every odd 32-bit word
// of the buffer is 0. For int32 data, P(64 uniform values in [0,200000) all
// equal 0) ~ 1e-339. Checked fresh every launch -> deterministic per input.
__global__ void ch_init_kernel(const int* __restrict__ nbr_words) {
    if (threadIdx.x == 0) {
        g_num = 0.0;
        g_den = 0.0;
        int allz = 1;
#pragma unroll
        for (int i = 1; i < 128; i += 2) allz &= (nbr_words[i] == 0);
        g_is64 = allz;
    }
}

__global__ __launch_bounds__(256) void ch_main_kernel(
    const float* __restrict__ feat,
    const int*   __restrict__ labels,
    const void*  __restrict__ nbr,
    int n)
{
    const unsigned FULL = 0xffffffffu;
    const int lane = threadIdx.x & 31;
    const int wid  = threadIdx.x >> 5;
    const int wp   = (blockIdx.x * blockDim.x + threadIdx.x) >> 5;   // warp -> point
    const bool active = (wp < n);
    const int p = active ? wp : 0;   // inactive warps compute garbage on point 0, masked out

    // center label (uniform broadcast load)
    const int lab = labels[p];

    // Quarter-warp layout: sublane s in [0,8) holds float4 chunk s of any row.
    const int s = lane & 7;
    const float4 cf = reinterpret_cast<const float4*>(feat + (size_t)p * CF)[s];

    // lanes 0..15: this lane's neighbor index and neighbor label
    int myidx = 0;
    if (lane < KNB) {
        if (g_is64)
            myidx = (int)reinterpret_cast<const long long*>(nbr)[(size_t)p * KNB + lane];
        else
            myidx = reinterpret_cast<const int*>(nbr)[(size_t)p * KNB + lane];
    }
    const int nblab = labels[(lane < KNB) ? myidx : 0];

    // Distances: iteration t handles neighbors t*4 .. t*4+3, one per 8-lane quarter.
    float dist2 = 0.0f;
#pragma unroll
    for (int t = 0; t < 4; t++) {
        const int j_src = t * 4 + (lane >> 3);                 // lane holding idx for my quarter's neighbor
        const int idx = __shfl_sync(FULL, myidx, j_src);
        const float4 nf = reinterpret_cast<const float4*>(feat + (size_t)idx * CF)[s];
        const float d0 = cf.x - nf.x, d1 = cf.y - nf.y;
        const float d2 = cf.z - nf.z, d3 = cf.w - nf.w;
        float sum = d0 * d0 + d1 * d1 + d2 * d2 + d3 * d3;
        sum += __shfl_xor_sync(FULL, sum, 4);
        sum += __shfl_xor_sync(FULL, sum, 2);
        sum += __shfl_xor_sync(FULL, sum, 1);
        // route quarter q's total (resident at lane q*8) to lane t*4+q
        const float cand = __shfl_sync(FULL, sum, (lane & 3) << 3);
        if ((lane >> 2) == t) dist2 = cand;
    }

    // lanes 0..15 now hold dist^2 for neighbor `lane`
    const float nd = (lane < KNB) ? -sqrtf(dist2 + 1e-8f) : -1e30f;

    // stable softmax: max over the 16 neighbor lanes (xor<16 never crosses halves)
    float m = nd;
    m = fmaxf(m, __shfl_xor_sync(FULL, m, 8));
    m = fmaxf(m, __shfl_xor_sync(FULL, m, 4));
    m = fmaxf(m, __shfl_xor_sync(FULL, m, 2));
    m = fmaxf(m, __shfl_xor_sync(FULL, m, 1));

    const float e = (lane < KNB) ? __expf((nd - m) * 10.0f) : 0.0f;   // 1/T = 10
    const float isp = (lane < KNB && nblab == lab) ? 1.0f : 0.0f;
    float pos = e * isp;
    float neg = e;
    float cnt = isp;
#pragma unroll
    for (int off = 8; off >= 1; off >>= 1) {
        pos += __shfl_xor_sync(FULL, pos, off);
        neg += __shfl_xor_sync(FULL, neg, off);
        cnt += __shfl_xor_sync(FULL, cnt, off);
    }

    __shared__ float s_num[8];
    __shared__ float s_den[8];
    if (lane == 0) {
        const float pm = (active && cnt > 0.5f && cnt < (float)KNB - 0.5f) ? 1.0f : 0.0f;
        const float loss = -__logf(pos / neg + 1e-8f);
        s_num[wid] = loss * pm;
        s_den[wid] = pm;
    }
    __syncthreads();
    if (threadIdx.x == 0) {
        float a = 0.0f, b = 0.0f;
#pragma unroll
        for (int i = 0; i < 8; i++) { a += s_num[i]; b += s_den[i]; }
        atomicAdd(&g_num, (double)a);
        atomicAdd(&g_den, (double)b);
    }
}

__global__ void ch_finalize_kernel(float* __restrict__ out) {
    if (threadIdx.x == 0) {
        double den = g_den;
        if (den < 1.0) den = 1.0;
        out[0] = (float)(g_num / den * 0.1);   // WEIGHT = 0.1
    }
}

extern "C" void kernel_launch(void* const* d_in, const int* in_sizes, int n_in,
                              void* d_out, int out_size) {
    const float* feat   = (const float*)d_in[0];
    const int*   labels = (const int*)d_in[1];
    const void*  nbr    = (const void*)d_in[2];
    float* out = (float*)d_out;

    const int n = in_sizes[1];            // N points (labels element count)
    (void)n_in; (void)out_size;

    ch_init_kernel<<<1, 32>>>((const int*)nbr);

    const int warps_per_block = 256 / 32;                 // 8 points per block
    const int blocks = (n + warps_per_block - 1) / warps_per_block;
    ch_main_kernel<<<blocks, 256>>>(feat, labels, nbr, n);

    ch_finalize_kernel<<<1, 32>>>(out);
}